// round 15
// baseline (speedup 1.0000x reference)
#include <cuda_runtime.h>
#include <cstdint>

typedef unsigned long long u64;

#define KH 3
#define KW 3
#define IN_C 3
#define OUT_C 16
#define QUBITS 5
#define DIM 32
#define FEAT 27
#define EPSV 0.001f
#define IMG 224
#define BATCH 8
#define CG 4            // channels per thread
#define PX 4            // pixels per thread

// Weight table in constant memory: (Re U[k,f], Im U[k,f]) packed as u64 per (f,k).
// Written directly by the setup kernel (address passed as kernel arg); read
// warp-uniform by the main kernel via the constant port (LDC.128).
__constant__ u64 c_W[FEAT * OUT_C];

// ---------------- packed f32x2 helpers ----------------
__device__ __forceinline__ u64 pack2(float lo, float hi) {
    u64 r; asm("mov.b64 %0, {%1, %2};" : "=l"(r) : "f"(lo), "f"(hi)); return r;
}
__device__ __forceinline__ void unpack2(u64 v, float& lo, float& hi) {
    asm("mov.b64 {%0, %1}, %2;" : "=f"(lo), "=f"(hi) : "l"(v));
}
__device__ __forceinline__ u64 fma2(u64 a, u64 b, u64 c) {
    u64 d; asm("fma.rn.f32x2 %0, %1, %2, %3;" : "=l"(d) : "l"(a), "l"(b), "l"(c)); return d;
}

// ---------------- setup: warp-per-column circuit simulation ----------------
// Warp f (threadIdx.y) simulates the circuit on basis state e_f; lane l holds
// amplitude of basis state l. Writes packed (Re,Im) directly into c_W storage.
__global__ void qconv_setup_kernel(const float* __restrict__ w, u64* __restrict__ wout) {
    const int f    = threadIdx.y;      // 0..26 column
    const int lane = threadIdx.x;      // 0..31 basis state
    float ar = (lane == f) ? 1.0f : 0.0f;
    float ai = 0.0f;

    // Rot(phi,theta,omega) = RZ(omega) RY(theta) RZ(phi) on each qubit
#pragma unroll
    for (int q = 0; q < QUBITS; q++) {
        const float phi = __ldg(&w[3 * q + 0]);
        const float th  = __ldg(&w[3 * q + 1]);
        const float om  = __ldg(&w[3 * q + 2]);
        const float ch = cosf(0.5f * th), sh = sinf(0.5f * th);
        const float ap = 0.5f * (phi + om), am = 0.5f * (phi - om);
        const float cap = cosf(ap), sap = sinf(ap);
        const float cam = cosf(am), sam = sinf(am);
        const float u00r =  ch * cap, u00i = -ch * sap;
        const float u01r = -sh * cam, u01i = -sh * sam;
        const float u10r =  sh * cam, u10i = -sh * sam;
        const float u11r =  ch * cap, u11i =  ch * sap;
        const int m = 1 << (4 - q);
        const float pr = __shfl_xor_sync(0xFFFFFFFFu, ar, m);
        const float pi = __shfl_xor_sync(0xFFFFFFFFu, ai, m);
        float nr, ni;
        if (lane & m) {   // |1> component: partner is |0>
            nr = u10r * pr - u10i * pi + u11r * ar - u11i * ai;
            ni = u10r * pi + u10i * pr + u11r * ai + u11i * ar;
        } else {          // |0> component: partner is |1>
            nr = u00r * ar - u00i * ai + u01r * pr - u01i * pi;
            ni = u00r * ai + u00i * ar + u01r * pi + u01i * pr;
        }
        ar = nr; ai = ni;
    }

    // CNOT ring: control q -> target (q+1)%5
#pragma unroll
    for (int q = 0; q < QUBITS; q++) {
        const int mc = 1 << (4 - q);
        const int mt = 1 << (4 - ((q + 1) % QUBITS));
        const float pr = __shfl_xor_sync(0xFFFFFFFFu, ar, mt);
        const float pi = __shfl_xor_sync(0xFFFFFFFFu, ai, mt);
        if (lane & mc) { ar = pr; ai = pi; }
    }

    if (lane < OUT_C)
        wout[f * OUT_C + lane] = pack2(ar, ai);

    // Make weight writes globally visible, then release the dependent launch.
    __threadfence();
    __syncthreads();
    asm volatile("griddepcontrol.launch_dependents;");
}

// ---------------- main: 4 pixels x 4 channels, fully unrolled 27 taps ----------------
__global__ __launch_bounds__(256, 4) void qconv_main_kernel(const float* __restrict__ x,
                                                            float* __restrict__ out) {
    const int t   = blockIdx.x * 256 + threadIdx.x;   // pixel-quad index
    const int w0  = (t % (IMG / PX)) * PX;            // multiple of 4
    const int row = t / (IMG / PX);
    const int h   = row % IMG;
    const int b   = row / IMG;
    const int kbase = blockIdx.y * CG;

    u64 acc[PX][CG];
#pragma unroll
    for (int p = 0; p < PX; p++)
#pragma unroll
        for (int k = 0; k < CG; k++) acc[p][k] = 0ull;
    float S[PX + 2];                                  // per-column square sums
#pragma unroll
    for (int i = 0; i < PX + 2; i++) S[i] = 0.0f;

    const float* xb = x + (size_t)b * IN_C * IMG * IMG;
    const u64* cWg = c_W + kbase;
    const bool le  = (w0 > 0);
    const bool re_ = (w0 < IMG - PX);

    // Wait for setup's weight writes (PDL edge) before any constant read.
    asm volatile("griddepcontrol.wait;" ::: "memory");

#pragma unroll
    for (int c = 0; c < IN_C; c++) {
#pragma unroll
        for (int di = 0; di < KH; di++) {
            const int y = h + di - 1;
            const bool ok = ((unsigned)y < (unsigned)IMG);
            const float* rp = xb + ((size_t)c * IMG + y) * IMG + w0;
            float te[PX + 2];
            if (ok) {
                const float4 q = *reinterpret_cast<const float4*>(rp);
                te[0] = le  ? __ldg(rp - 1) : 0.0f;
                te[1] = q.x; te[2] = q.y; te[3] = q.z; te[4] = q.w;
                te[5] = re_ ? __ldg(rp + PX) : 0.0f;
            } else {
#pragma unroll
                for (int i = 0; i < PX + 2; i++) te[i] = 0.0f;
            }
            u64 dup[PX + 2];
#pragma unroll
            for (int i = 0; i < PX + 2; i++) {
                te[i] += EPSV;
                S[i] = fmaf(te[i], te[i], S[i]);
                dup[i] = pack2(te[i], te[i]);
            }
#pragma unroll
            for (int dj = 0; dj < KW; dj++) {
                const u64* wr = &cWg[(c * 9 + di * 3 + dj) * OUT_C];
                const ulonglong2 w01 = *reinterpret_cast<const ulonglong2*>(&wr[0]); // LDC.128
                const ulonglong2 w23 = *reinterpret_cast<const ulonglong2*>(&wr[2]); // LDC.128
#pragma unroll
                for (int p = 0; p < PX; p++) {
                    const u64 vv = dup[p + dj];
                    acc[p][0] = fma2(w01.x, vv, acc[p][0]);
                    acc[p][1] = fma2(w01.y, vv, acc[p][1]);
                    acc[p][2] = fma2(w23.x, vv, acc[p][2]);
                    acc[p][3] = fma2(w23.y, vv, acc[p][3]);
                }
            }
        }
    }

    float rn[PX];
#pragma unroll
    for (int p = 0; p < PX; p++)
        rn[p] = __fdividef(8.0f, S[p] + S[p + 1] + S[p + 2]);

    float* ob = out + (size_t)b * OUT_C * IMG * IMG + (size_t)kbase * (IMG * IMG)
              + (size_t)h * IMG + w0;
#pragma unroll
    for (int k = 0; k < CG; k++) {
        float4 o;
        float* ov = reinterpret_cast<float*>(&o);
#pragma unroll
        for (int p = 0; p < PX; p++) {
            float R, I;
            unpack2(acc[p][k], R, I);
            ov[p] = fmaf(R, R, I * I) * rn[p];
        }
        *reinterpret_cast<float4*>(ob + (size_t)k * (IMG * IMG)) = o;   // 16B-aligned
    }
}

extern "C" void kernel_launch(void* const* d_in, const int* in_sizes, int n_in,
                              void* d_out, int out_size) {
    const float* x = (const float*)d_in[0];       // (8,3,224,224) float32
    const float* w = (const float*)d_in[1];       // (1,5,3) float32
    float* out = (float*)d_out;                   // (8,16,224,224) float32
    (void)in_sizes; (void)n_in; (void)out_size;

    // Setup kernel writes weights straight into c_W's backing storage.
    void* cw = nullptr;
    cudaGetSymbolAddress(&cw, c_W);
    qconv_setup_kernel<<<1, dim3(32, FEAT)>>>(w, (u64*)cw);

    // Main kernel with programmatic dependent launch (overlaps launch latency
    // with the setup kernel; griddepcontrol.wait orders the weight reads).
    const int nquads = BATCH * IMG * (IMG / PX);  // 100352
    cudaLaunchConfig_t cfg = {};
    cfg.gridDim  = dim3(nquads / 256, OUT_C / CG);   // (392, 4)
    cfg.blockDim = dim3(256, 1, 1);
    cudaLaunchAttribute attrs[1];
    attrs[0].id = cudaLaunchAttributeProgrammaticStreamSerialization;
    attrs[0].val.programmaticStreamSerializationAllowed = 1;
    cfg.attrs = attrs;
    cfg.numAttrs = 1;
    cudaLaunchKernelEx(&cfg, qconv_main_kernel, x, out);
}

// round 16
// speedup vs baseline: 1.0651x; 1.0651x over previous
#include <cuda_runtime.h>
#include <cstdint>

typedef unsigned long long u64;

#define KH 3
#define KW 3
#define IN_C 3
#define OUT_C 16
#define QUBITS 5
#define DIM 32
#define FEAT 27
#define EPSV 0.001f
#define IMG 224
#define BATCH 8
#define CG 4            // channels per thread
#define PX 4            // pixels per thread

// Weight table in constant memory: (Re U[k,f], Im U[k,f]) packed as u64 per (f,k).
// Written directly by the setup kernel (address passed as kernel arg); read
// warp-uniform by the main kernel via the constant port (LDC.128).
__constant__ u64 c_W[FEAT * OUT_C];

// ---------------- packed f32x2 helpers ----------------
__device__ __forceinline__ u64 pack2(float lo, float hi) {
    u64 r; asm("mov.b64 %0, {%1, %2};" : "=l"(r) : "f"(lo), "f"(hi)); return r;
}
__device__ __forceinline__ void unpack2(u64 v, float& lo, float& hi) {
    asm("mov.b64 {%0, %1}, %2;" : "=f"(lo), "=f"(hi) : "l"(v));
}
__device__ __forceinline__ u64 fma2(u64 a, u64 b, u64 c) {
    u64 d; asm("fma.rn.f32x2 %0, %1, %2, %3;" : "=l"(d) : "l"(a), "l"(b), "l"(c)); return d;
}

// ---------------- setup: warp-per-column circuit simulation ----------------
// Warp f (threadIdx.y) simulates the circuit on basis state e_f; lane l holds
// amplitude of basis state l. Writes packed (Re,Im) directly into c_W storage.
__global__ void qconv_setup_kernel(const float* __restrict__ w, u64* __restrict__ wout) {
    const int f    = threadIdx.y;      // 0..26 column
    const int lane = threadIdx.x;      // 0..31 basis state
    float ar = (lane == f) ? 1.0f : 0.0f;
    float ai = 0.0f;

    // Rot(phi,theta,omega) = RZ(omega) RY(theta) RZ(phi) on each qubit
#pragma unroll
    for (int q = 0; q < QUBITS; q++) {
        const float phi = __ldg(&w[3 * q + 0]);
        const float th  = __ldg(&w[3 * q + 1]);
        const float om  = __ldg(&w[3 * q + 2]);
        const float ch = cosf(0.5f * th), sh = sinf(0.5f * th);
        const float ap = 0.5f * (phi + om), am = 0.5f * (phi - om);
        const float cap = cosf(ap), sap = sinf(ap);
        const float cam = cosf(am), sam = sinf(am);
        const float u00r =  ch * cap, u00i = -ch * sap;
        const float u01r = -sh * cam, u01i = -sh * sam;
        const float u10r =  sh * cam, u10i = -sh * sam;
        const float u11r =  ch * cap, u11i =  ch * sap;
        const int m = 1 << (4 - q);
        const float pr = __shfl_xor_sync(0xFFFFFFFFu, ar, m);
        const float pi = __shfl_xor_sync(0xFFFFFFFFu, ai, m);
        float nr, ni;
        if (lane & m) {   // |1> component: partner is |0>
            nr = u10r * pr - u10i * pi + u11r * ar - u11i * ai;
            ni = u10r * pi + u10i * pr + u11r * ai + u11i * ar;
        } else {          // |0> component: partner is |1>
            nr = u00r * ar - u00i * ai + u01r * pr - u01i * pi;
            ni = u00r * ai + u00i * ar + u01r * pi + u01i * pr;
        }
        ar = nr; ai = ni;
    }

    // CNOT ring: control q -> target (q+1)%5
#pragma unroll
    for (int q = 0; q < QUBITS; q++) {
        const int mc = 1 << (4 - q);
        const int mt = 1 << (4 - ((q + 1) % QUBITS));
        const float pr = __shfl_xor_sync(0xFFFFFFFFu, ar, mt);
        const float pi = __shfl_xor_sync(0xFFFFFFFFu, ai, mt);
        if (lane & mc) { ar = pr; ai = pi; }
    }

    if (lane < OUT_C)
        wout[f * OUT_C + lane] = pack2(ar, ai);

    // Make weight writes globally visible, then release the dependent launch.
    __threadfence();
    __syncthreads();
    asm volatile("griddepcontrol.launch_dependents;");
}

// ---------------- main: 4 pixels x 4 channels, fully unrolled 27 taps ----------------
__global__ __launch_bounds__(256, 4) void qconv_main_kernel(const float* __restrict__ x,
                                                            float* __restrict__ out) {
    const int t   = blockIdx.x * 256 + threadIdx.x;   // pixel-quad index
    const int w0  = (t % (IMG / PX)) * PX;            // multiple of 4
    const int row = t / (IMG / PX);
    const int h   = row % IMG;
    const int b   = row / IMG;
    const int kbase = blockIdx.y * CG;

    u64 acc[PX][CG];
#pragma unroll
    for (int p = 0; p < PX; p++)
#pragma unroll
        for (int k = 0; k < CG; k++) acc[p][k] = 0ull;
    float S[PX + 2];                                  // per-column square sums
#pragma unroll
    for (int i = 0; i < PX + 2; i++) S[i] = 0.0f;

    const float* xb = x + (size_t)b * IN_C * IMG * IMG;
    const u64* cWg = c_W + kbase;
    const bool le  = (w0 > 0);
    const bool re_ = (w0 < IMG - PX);

    // Wait for setup's weight writes (PDL edge) before any constant read.
    asm volatile("griddepcontrol.wait;" ::: "memory");

#pragma unroll
    for (int c = 0; c < IN_C; c++) {
#pragma unroll
        for (int di = 0; di < KH; di++) {
            const int y = h + di - 1;
            const bool ok = ((unsigned)y < (unsigned)IMG);
            const float* rp = xb + ((size_t)c * IMG + y) * IMG + w0;
            float te[PX + 2];
            if (ok) {
                const float4 q = *reinterpret_cast<const float4*>(rp);
                te[0] = le  ? __ldg(rp - 1) : 0.0f;
                te[1] = q.x; te[2] = q.y; te[3] = q.z; te[4] = q.w;
                te[5] = re_ ? __ldg(rp + PX) : 0.0f;
            } else {
#pragma unroll
                for (int i = 0; i < PX + 2; i++) te[i] = 0.0f;
            }
            u64 dup[PX + 2];
#pragma unroll
            for (int i = 0; i < PX + 2; i++) {
                te[i] += EPSV;
                S[i] = fmaf(te[i], te[i], S[i]);
                dup[i] = pack2(te[i], te[i]);
            }
#pragma unroll
            for (int dj = 0; dj < KW; dj++) {
                const u64* wr = &cWg[(c * 9 + di * 3 + dj) * OUT_C];
                const ulonglong2 w01 = *reinterpret_cast<const ulonglong2*>(&wr[0]); // LDC.128
                const ulonglong2 w23 = *reinterpret_cast<const ulonglong2*>(&wr[2]); // LDC.128
#pragma unroll
                for (int p = 0; p < PX; p++) {
                    const u64 vv = dup[p + dj];
                    acc[p][0] = fma2(w01.x, vv, acc[p][0]);
                    acc[p][1] = fma2(w01.y, vv, acc[p][1]);
                    acc[p][2] = fma2(w23.x, vv, acc[p][2]);
                    acc[p][3] = fma2(w23.y, vv, acc[p][3]);
                }
            }
        }
    }

    float rn[PX];
#pragma unroll
    for (int p = 0; p < PX; p++)
        rn[p] = __fdividef(8.0f, S[p] + S[p + 1] + S[p + 2]);

    float* ob = out + (size_t)b * OUT_C * IMG * IMG + (size_t)kbase * (IMG * IMG)
              + (size_t)h * IMG + w0;
#pragma unroll
    for (int k = 0; k < CG; k++) {
        float4 o;
        float* ov = reinterpret_cast<float*>(&o);
#pragma unroll
        for (int p = 0; p < PX; p++) {
            float R, I;
            unpack2(acc[p][k], R, I);
            ov[p] = fmaf(R, R, I * I) * rn[p];
        }
        *reinterpret_cast<float4*>(ob + (size_t)k * (IMG * IMG)) = o;   // 16B-aligned
    }
}

extern "C" void kernel_launch(void* const* d_in, const int* in_sizes, int n_in,
                              void* d_out, int out_size) {
    const float* x = (const float*)d_in[0];       // (8,3,224,224) float32
    const float* w = (const float*)d_in[1];       // (1,5,3) float32
    float* out = (float*)d_out;                   // (8,16,224,224) float32
    (void)in_sizes; (void)n_in; (void)out_size;

    // Setup kernel writes weights straight into c_W's backing storage.
    void* cw = nullptr;
    cudaGetSymbolAddress(&cw, c_W);
    qconv_setup_kernel<<<1, dim3(32, FEAT)>>>(w, (u64*)cw);

    // Main kernel with programmatic dependent launch (overlaps launch latency
    // with the setup kernel; griddepcontrol.wait orders the weight reads).
    const int nquads = BATCH * IMG * (IMG / PX);  // 100352
    cudaLaunchConfig_t cfg = {};
    cfg.gridDim  = dim3(nquads / 256, OUT_C / CG);   // (392, 4)
    cfg.blockDim = dim3(256, 1, 1);
    cudaLaunchAttribute attrs[1];
    attrs[0].id = cudaLaunchAttributeProgrammaticStreamSerialization;
    attrs[0].val.programmaticStreamSerializationAllowed = 1;
    cfg.attrs = attrs;
    cfg.numAttrs = 1;
    cudaLaunchKernelEx(&cfg, qconv_main_kernel, x, out);
}